// round 1
// baseline (speedup 1.0000x reference)
#include <cuda_runtime.h>

#define C 256
#define H 8
#define DH 32
#define NUM_DST 256
#define NMAX 50000
#define EMAX 300000
#define LISTCAP 8192
#define INV_SQRT_DH 0.17677669529663687f  // 1/sqrt(32)
#define LN_EPS 1e-5f

__device__ int g_deg[NMAX];
__device__ int g_bcount[NUM_DST];
__device__ int g_bstart[NUM_DST];
__device__ int g_bcursor[NUM_DST];
__device__ int g_listcount;
__device__ int g_list[LISTCAP];
__device__ unsigned char g_spd[EMAX];
__device__ int g_ssrc[EMAX];
__device__ int g_seid[EMAX];
__device__ float g_u[NUM_DST * H * C];
__device__ float g_c0[NUM_DST * H];
__device__ float g_outsmall[NUM_DST * C];

// ---------------------------------------------------------------------------
// K0: init counters / spd
__global__ void k_init(int n, int e) {
    int i = blockIdx.x * blockDim.x + threadIdx.x;
    if (i < n) g_deg[i] = 0;
    if (i < e) g_spd[i] = 4;  // MAX_SPD + 1
    if (i < NUM_DST) g_bcount[i] = 0;
    if (i == 0) g_listcount = 0;
}

// ---------------------------------------------------------------------------
// K1: degree counts, per-dst bucket counts, compact list of src<256 edges
__global__ void k_scan(const int* __restrict__ src, const int* __restrict__ dst, int e) {
    int i = blockIdx.x * blockDim.x + threadIdx.x;
    if (i >= e) return;
    int s = src[i], d = dst[i];
    atomicAdd(&g_deg[s], 1);
    atomicAdd(&g_bcount[d], 1);
    if (s < NUM_DST) {
        int p = atomicAdd(&g_listcount, 1);
        if (p < LISTCAP) g_list[p] = i;
    }
}

// ---------------------------------------------------------------------------
// K2: exclusive prefix sum over 256 bucket counts; fold in-degree into deg
__global__ void k_prefix() {
    __shared__ int tmp[NUM_DST];
    int t = threadIdx.x;
    int cnt = g_bcount[t];
    tmp[t] = cnt;
    __syncthreads();
    // inclusive scan
    for (int off = 1; off < NUM_DST; off <<= 1) {
        int v = (t >= off) ? tmp[t - off] : 0;
        __syncthreads();
        tmp[t] += v;
        __syncthreads();
    }
    int excl = tmp[t] - cnt;
    g_bstart[t] = excl;
    g_bcursor[t] = excl;
    g_deg[t] += cnt;  // in-degree contribution (dst < 256 always)
}

// ---------------------------------------------------------------------------
// K3: scatter edges into dst buckets (order within bucket arbitrary)
__global__ void k_scatter(const int* __restrict__ src, const int* __restrict__ dst, int e) {
    int i = blockIdx.x * blockDim.x + threadIdx.x;
    if (i >= e) return;
    int d = dst[i];
    int p = atomicAdd(&g_bcursor[d], 1);
    g_ssrc[p] = src[i];
    g_seid[p] = i;
}

// ---------------------------------------------------------------------------
// K4: reverse-BFS shortest-path buckets. F is a 256x256 bitmatrix (rows < 256
// only, since row index = dst < 256). Only edges with src<256 matter.
__global__ void k_bfs(const int* __restrict__ src, const int* __restrict__ dst) {
    __shared__ unsigned F0[NUM_DST][8];
    __shared__ unsigned F1[NUM_DST][8];
    int t = threadIdx.x;
    #pragma unroll
    for (int w = 0; w < 8; w++)
        F0[t][w] = (w == (t >> 5)) ? (1u << (t & 31)) : 0u;
    int cnt = g_listcount;
    if (cnt > LISTCAP) cnt = LISTCAP;
    __syncthreads();
    for (int k = 1; k <= 3; k++) {
        #pragma unroll
        for (int w = 0; w < 8; w++) F1[t][w] = 0u;
        __syncthreads();
        for (int i = t; i < cnt; i += 256) {
            int e = g_list[i];
            int s = src[e], d = dst[e];
            #pragma unroll
            for (int w = 0; w < 8; w++) {
                unsigned v = F0[s][w];
                if (v) atomicOr(&F1[d][w], v);
            }
        }
        __syncthreads();
        for (int i = t; i < cnt; i += 256) {
            int e = g_list[i];
            int s = src[e], d = dst[e];
            if (g_spd[e] == 4 && ((F1[s][d >> 5] >> (d & 31)) & 1u))
                g_spd[e] = (unsigned char)k;
        }
        __syncthreads();
        #pragma unroll
        for (int w = 0; w < 8; w++) F0[t][w] = F1[t][w];
        __syncthreads();
    }
}

// ---------------------------------------------------------------------------
// K5: per-dst precompute. Q[d] = x[d]@Wq^T + bq (256 floats), then fold into
// u[d][h][k] = sum_j Q[32h+j] * Wk[32h+j][k], c0[d][h] = sum_j Q[32h+j]*bk[...]
__global__ void k_qu(const float* __restrict__ x,
                     const float* __restrict__ Wq, const float* __restrict__ bq,
                     const float* __restrict__ Wk, const float* __restrict__ bk) {
    int d = blockIdx.x;
    int t = threadIdx.x, lane = t & 31, wp = t >> 5;
    __shared__ float xs[C], qs[C];
    xs[t] = x[d * C + t];
    __syncthreads();
    // q[j]: one warp per output, coalesced Wq row reads, butterfly reduce
    for (int j = wp; j < C; j += 8) {
        const float* wr = Wq + j * C;
        float p = 0.f;
        #pragma unroll
        for (int i = 0; i < 8; i++) p += wr[lane + 32 * i] * xs[lane + 32 * i];
        #pragma unroll
        for (int o = 16; o; o >>= 1) p += __shfl_xor_sync(0xffffffffu, p, o);
        if (lane == 0) qs[j] = p + bq[j];
    }
    __syncthreads();
    // u[h][k], thread t = column k, coalesced Wk row reads
    #pragma unroll
    for (int h = 0; h < H; h++) {
        float acc = 0.f;
        #pragma unroll 8
        for (int j = 0; j < 32; j++)
            acc += qs[h * 32 + j] * Wk[(h * 32 + j) * C + t];
        g_u[d * H * C + h * C + t] = acc;
    }
    if (t < H) {
        float s = 0.f;
        #pragma unroll
        for (int j = 0; j < 32; j++) s += qs[t * 32 + j] * bk[t * 32 + j];
        g_c0[d * H + t] = s;
    }
}

// ---------------------------------------------------------------------------
// K6: per-dst fused attention. One block per dst. Online softmax per warp,
// per-head aggregation of raw x[src] (Wv applied after aggregation since
// softmax weights sum to 1 per head).
__global__ __launch_bounds__(256, 1)
void k_attn(const float* __restrict__ x,
            const float* __restrict__ Wv, const float* __restrict__ bv,
            const float* __restrict__ spd_w) {
    int d = blockIdx.x;
    int t = threadIdx.x, lane = t & 31, wp = t >> 5;
    __shared__ float us[H][C];       // u[d] * INV_SQRT_DH
    __shared__ float sw[5][H];
    __shared__ float agg[H][C];
    __shared__ float c0s[H];
    __shared__ float msh[8][H], lsh[8][H];
    __shared__ float Msh[H], Linv[H];

    for (int i = t; i < H * C; i += 256)
        ((float*)us)[i] = g_u[d * H * C + i] * INV_SQRT_DH;
    if (t < 40) ((float*)sw)[t] = spd_w[t];
    if (t < H) c0s[t] = g_c0[d * H + t] * INV_SQRT_DH;
    for (int i = t; i < H * C; i += 256) ((float*)agg)[i] = 0.f;
    __syncthreads();

    int start = g_bstart[d], cnt = g_bcount[d];
    if (cnt == 0) {
        for (int i = t; i < C; i += 256) g_outsmall[d * C + i] = 0.f;
        return;
    }

    float m[H], l[H], acc[H][8];
    #pragma unroll
    for (int h = 0; h < H; h++) {
        m[h] = -1e30f; l[h] = 0.f;
        #pragma unroll
        for (int j = 0; j < 8; j++) acc[h][j] = 0.f;
    }

    for (int i = start + wp; i < start + cnt; i += 8) {
        int s = g_ssrc[i];
        int sp = g_spd[g_seid[i]];
        const float* xr = x + (size_t)s * C + lane * 8;
        float4 a = *(const float4*)(xr);
        float4 b = *(const float4*)(xr + 4);
        float xv[8] = {a.x, a.y, a.z, a.w, b.x, b.y, b.z, b.w};
        float p[H];
        #pragma unroll
        for (int h = 0; h < H; h++) {
            float q = 0.f;
            #pragma unroll
            for (int j = 0; j < 8; j++) q += xv[j] * us[h][lane * 8 + j];
            p[h] = q;
        }
        #pragma unroll
        for (int o = 16; o; o >>= 1) {
            #pragma unroll
            for (int h = 0; h < H; h++) p[h] += __shfl_xor_sync(0xffffffffu, p[h], o);
        }
        #pragma unroll
        for (int h = 0; h < H; h++) {
            float sc = p[h] + c0s[h] + sw[sp][h];
            if (sc <= m[h]) {
                float w = __expf(sc - m[h]);
                l[h] += w;
                #pragma unroll
                for (int j = 0; j < 8; j++) acc[h][j] += w * xv[j];
            } else {
                float r = __expf(m[h] - sc);
                l[h] = l[h] * r + 1.f;
                #pragma unroll
                for (int j = 0; j < 8; j++) acc[h][j] = acc[h][j] * r + xv[j];
                m[h] = sc;
            }
        }
    }

    // combine warp-local online-softmax states
    if (lane == 0) {
        #pragma unroll
        for (int h = 0; h < H; h++) { msh[wp][h] = m[h]; lsh[wp][h] = l[h]; }
    }
    __syncthreads();
    if (t < H) {
        float M = -1e30f;
        #pragma unroll
        for (int w8 = 0; w8 < 8; w8++) M = fmaxf(M, msh[w8][t]);
        float L = 0.f;
        #pragma unroll
        for (int w8 = 0; w8 < 8; w8++) L += lsh[w8][t] * __expf(msh[w8][t] - M);
        Msh[t] = M;
        Linv[t] = 1.f / L;
    }
    __syncthreads();
    #pragma unroll
    for (int h = 0; h < H; h++) {
        float f = __expf(m[h] - Msh[h]);
        #pragma unroll
        for (int j = 0; j < 8; j++)
            atomicAdd(&agg[h][lane * 8 + j], acc[h][j] * f);
    }
    __syncthreads();

    // final V projection: out[c] = (agg[h]/L) . Wv[c,:] + bv[c], h = c/32
    float linv = Linv[wp];
    for (int r = 0; r < 32; r++) {
        int c = wp * 32 + r;
        const float* wr = Wv + c * C + lane * 8;
        float4 wa = *(const float4*)(wr);
        float4 wb = *(const float4*)(wr + 4);
        float pacc = wa.x * agg[wp][lane * 8 + 0] + wa.y * agg[wp][lane * 8 + 1]
                   + wa.z * agg[wp][lane * 8 + 2] + wa.w * agg[wp][lane * 8 + 3]
                   + wb.x * agg[wp][lane * 8 + 4] + wb.y * agg[wp][lane * 8 + 5]
                   + wb.z * agg[wp][lane * 8 + 6] + wb.w * agg[wp][lane * 8 + 7];
        #pragma unroll
        for (int o = 16; o; o >>= 1) pacc += __shfl_xor_sync(0xffffffffu, pacc, o);
        if (lane == 0) g_outsmall[d * C + c] = pacc * linv + bv[c];
    }
}

// ---------------------------------------------------------------------------
// K7: residual + degree + LayerNorm. One warp per row.
__global__ void k_ln(const float* __restrict__ x,
                     const float* __restrict__ gamma, const float* __restrict__ beta,
                     float* __restrict__ out, int n) {
    int row = blockIdx.x * 8 + (threadIdx.x >> 5);
    int lane = threadIdx.x & 31;
    if (row >= n) return;
    const float* xr = x + (size_t)row * C + lane * 8;
    float4 a = *(const float4*)(xr);
    float4 b = *(const float4*)(xr + 4);
    float v[8] = {a.x, a.y, a.z, a.w, b.x, b.y, b.z, b.w};
    float degf = (float)g_deg[row];
    #pragma unroll
    for (int j = 0; j < 8; j++) v[j] += degf;
    if (row < NUM_DST) {
        const float* orow = g_outsmall + row * C + lane * 8;
        float4 oa = *(const float4*)(orow);
        float4 ob = *(const float4*)(orow + 4);
        v[0] += oa.x; v[1] += oa.y; v[2] += oa.z; v[3] += oa.w;
        v[4] += ob.x; v[5] += ob.y; v[6] += ob.z; v[7] += ob.w;
    }
    float s = 0.f;
    #pragma unroll
    for (int j = 0; j < 8; j++) s += v[j];
    #pragma unroll
    for (int o = 16; o; o >>= 1) s += __shfl_xor_sync(0xffffffffu, s, o);
    float mu = s * (1.f / C);
    float q = 0.f;
    #pragma unroll
    for (int j = 0; j < 8; j++) { float dd = v[j] - mu; q += dd * dd; }
    #pragma unroll
    for (int o = 16; o; o >>= 1) q += __shfl_xor_sync(0xffffffffu, q, o);
    float rstd = rsqrtf(q * (1.f / C) + LN_EPS);
    const float* gr = gamma + lane * 8;
    const float* br = beta + lane * 8;
    float4 g1 = *(const float4*)(gr);
    float4 g2 = *(const float4*)(gr + 4);
    float4 b1 = *(const float4*)(br);
    float4 b2 = *(const float4*)(br + 4);
    float gv[8] = {g1.x, g1.y, g1.z, g1.w, g2.x, g2.y, g2.z, g2.w};
    float bvv[8] = {b1.x, b1.y, b1.z, b1.w, b2.x, b2.y, b2.z, b2.w};
    float o[8];
    #pragma unroll
    for (int j = 0; j < 8; j++) o[j] = (v[j] - mu) * rstd * gv[j] + bvv[j];
    float* orow = out + (size_t)row * C + lane * 8;
    *(float4*)(orow) = make_float4(o[0], o[1], o[2], o[3]);
    *(float4*)(orow + 4) = make_float4(o[4], o[5], o[6], o[7]);
}

// ---------------------------------------------------------------------------
extern "C" void kernel_launch(void* const* d_in, const int* in_sizes, int n_in,
                              void* d_out, int out_size) {
    const float* x     = (const float*)d_in[0];
    const int*   src   = (const int*)d_in[1];
    const int*   dst   = (const int*)d_in[2];
    const float* Wq    = (const float*)d_in[3];
    const float* bq    = (const float*)d_in[4];
    const float* Wk    = (const float*)d_in[5];
    const float* bk    = (const float*)d_in[6];
    const float* Wv    = (const float*)d_in[7];
    const float* bv    = (const float*)d_in[8];
    const float* spd_w = (const float*)d_in[9];
    const float* gamma = (const float*)d_in[10];
    const float* beta  = (const float*)d_in[11];
    float* out = (float*)d_out;

    int n = in_sizes[0] / C;
    int e = in_sizes[1];
    int mx = (n > e) ? n : e;

    k_init<<<(mx + 255) / 256, 256>>>(n, e);
    k_scan<<<(e + 255) / 256, 256>>>(src, dst, e);
    k_prefix<<<1, 256>>>();
    k_scatter<<<(e + 255) / 256, 256>>>(src, dst, e);
    k_bfs<<<1, 256>>>(src, dst);
    k_qu<<<NUM_DST, 256>>>(x, Wq, bq, Wk, bk);
    k_attn<<<NUM_DST, 256>>>(x, Wv, bv, spd_w);
    k_ln<<<(n + 7) / 8, 256>>>(x, gamma, beta, out, n);
}

// round 4
// speedup vs baseline: 1.5635x; 1.5635x over previous
#include <cuda_runtime.h>

#define C 256
#define H 8
#define DH 32
#define NUM_DST 256
#define NMAX 50000
#define EMAX 300000
#define LISTCAP 8192
#define HB 128            // histogram/scatter blocks
#define INV_SQRT_DH 0.17677669529663687f
#define LN_EPS 1e-5f

typedef unsigned long long u64;

__device__ int g_deg[NMAX];
__device__ int g_bcount[NUM_DST];
__device__ int g_bstart[NUM_DST];
__device__ int g_blockhist[HB * NUM_DST];
__device__ int g_blockbase[HB * NUM_DST];
__device__ int g_listcount;
__device__ int g_list[LISTCAP];
__device__ unsigned char g_spd[EMAX];
__device__ int2 g_sedge[EMAX];       // {src, eid} in dst-bucket order
__device__ float g_u[NUM_DST * H * C];
__device__ float g_c0[NUM_DST * H];
__device__ float g_outsmall[NUM_DST * C];

// ---- f32x2 packed helpers --------------------------------------------------
__device__ __forceinline__ u64 pack2(float lo, float hi) {
    u64 r; asm("mov.b64 %0, {%1, %2};" : "=l"(r) : "f"(lo), "f"(hi)); return r;
}
__device__ __forceinline__ void unpack2(u64 v, float& lo, float& hi) {
    asm("mov.b64 {%0, %1}, %2;" : "=f"(lo), "=f"(hi) : "l"(v));
}
__device__ __forceinline__ void fma2(u64& d, u64 a, u64 b) {
    asm("fma.rn.f32x2 %0, %1, %2, %3;" : "=l"(d) : "l"(a), "l"(b), "l"(d));
}

// ---------------------------------------------------------------------------
// K0: init
__global__ void k_init(int n, int e) {
    int i = blockIdx.x * blockDim.x + threadIdx.x;
    if (i < n) g_deg[i] = 0;
    if (i < e) g_spd[i] = 4;  // MAX_SPD + 1
    if (i == 0) g_listcount = 0;
}

// ---------------------------------------------------------------------------
// K1: block-local histograms + out-degree + src<256 list
__global__ void k_hist(const int* __restrict__ src, const int* __restrict__ dst, int e) {
    __shared__ int hist[NUM_DST];
    int t = threadIdx.x;
    hist[t] = 0;
    __syncthreads();
    for (int i = blockIdx.x * blockDim.x + t; i < e; i += gridDim.x * blockDim.x) {
        int s = src[i], d = dst[i];
        atomicAdd(&g_deg[s], 1);
        atomicAdd(&hist[d], 1);
        if (s < NUM_DST) {
            int p = atomicAdd(&g_listcount, 1);
            if (p < LISTCAP) g_list[p] = i;
        }
    }
    __syncthreads();
    g_blockhist[blockIdx.x * NUM_DST + t] = hist[t];
}

// ---------------------------------------------------------------------------
// K2: bucket totals, global scan, per-block bases, in-degree fold
__global__ void k_prefix() {
    __shared__ int tmp[NUM_DST];
    int t = threadIdx.x;
    int total = 0;
    for (int b = 0; b < HB; b++) total += g_blockhist[b * NUM_DST + t];
    tmp[t] = total;
    __syncthreads();
    for (int off = 1; off < NUM_DST; off <<= 1) {
        int v = (t >= off) ? tmp[t - off] : 0;
        __syncthreads();
        tmp[t] += v;
        __syncthreads();
    }
    int excl = tmp[t] - total;
    g_bstart[t] = excl;
    g_bcount[t] = total;
    g_deg[t] += total;  // in-degree (all dst < 256)
    int run = excl;
    for (int b = 0; b < HB; b++) {
        g_blockbase[b * NUM_DST + t] = run;
        run += g_blockhist[b * NUM_DST + t];
    }
}

// ---------------------------------------------------------------------------
// K3: scatter with smem cursors (same edge->block mapping as k_hist)
__global__ void k_scatter(const int* __restrict__ src, const int* __restrict__ dst, int e) {
    __shared__ int cur[NUM_DST];
    int t = threadIdx.x;
    cur[t] = g_blockbase[blockIdx.x * NUM_DST + t];
    __syncthreads();
    for (int i = blockIdx.x * blockDim.x + t; i < e; i += gridDim.x * blockDim.x) {
        int s = src[i], d = dst[i];
        int p = atomicAdd(&cur[d], 1);
        g_sedge[p] = make_int2(s, i);
    }
}

// ---------------------------------------------------------------------------
// K4: reverse-BFS spd buckets (256x256 bitmatrix; only src<256 edges matter)
__global__ void k_bfs(const int* __restrict__ src, const int* __restrict__ dst) {
    __shared__ unsigned F0[NUM_DST][8];
    __shared__ unsigned F1[NUM_DST][8];
    int t = threadIdx.x;
    #pragma unroll
    for (int w = 0; w < 8; w++)
        F0[t][w] = (w == (t >> 5)) ? (1u << (t & 31)) : 0u;
    int cnt = g_listcount;
    if (cnt > LISTCAP) cnt = LISTCAP;
    __syncthreads();
    for (int k = 1; k <= 3; k++) {
        #pragma unroll
        for (int w = 0; w < 8; w++) F1[t][w] = 0u;
        __syncthreads();
        for (int i = t; i < cnt; i += 256) {
            int e = g_list[i];
            int s = src[e], d = dst[e];
            #pragma unroll
            for (int w = 0; w < 8; w++) {
                unsigned v = F0[s][w];
                if (v) atomicOr(&F1[d][w], v);
            }
        }
        __syncthreads();
        for (int i = t; i < cnt; i += 256) {
            int e = g_list[i];
            int s = src[e], d = dst[e];
            if (g_spd[e] == 4 && ((F1[s][d >> 5] >> (d & 31)) & 1u))
                g_spd[e] = (unsigned char)k;
        }
        __syncthreads();
        #pragma unroll
        for (int w = 0; w < 8; w++) F0[t][w] = F1[t][w];
        __syncthreads();
    }
}

// ---------------------------------------------------------------------------
// K5: per-dst u/c0 precompute, pre-scaled by 1/sqrt(DH)
__global__ void k_qu(const float* __restrict__ x,
                     const float* __restrict__ Wq, const float* __restrict__ bq,
                     const float* __restrict__ Wk, const float* __restrict__ bk) {
    int d = blockIdx.x;
    int t = threadIdx.x, lane = t & 31, wp = t >> 5;
    __shared__ float xs[C], qs[C];
    xs[t] = x[d * C + t];
    __syncthreads();
    for (int j = wp; j < C; j += 8) {
        const float* wr = Wq + j * C;
        float p = 0.f;
        #pragma unroll
        for (int i = 0; i < 8; i++) p += wr[lane + 32 * i] * xs[lane + 32 * i];
        #pragma unroll
        for (int o = 16; o; o >>= 1) p += __shfl_xor_sync(0xffffffffu, p, o);
        if (lane == 0) qs[j] = p + bq[j];
    }
    __syncthreads();
    #pragma unroll
    for (int h = 0; h < H; h++) {
        float acc = 0.f;
        #pragma unroll 8
        for (int j = 0; j < 32; j++)
            acc += qs[h * 32 + j] * Wk[(h * 32 + j) * C + t];
        g_u[d * H * C + h * C + t] = acc * INV_SQRT_DH;
    }
    if (t < H) {
        float s = 0.f;
        #pragma unroll
        for (int j = 0; j < 32; j++) s += qs[t * 32 + j] * bk[t * 32 + j];
        g_c0[d * H + t] = s * INV_SQRT_DH;
    }
}

// ---------------------------------------------------------------------------
// K6: per-dst fused attention. No online max (scores provably bounded);
// pure weighted sums -> trivially parallel. Head-folding shfl reduce (9),
// owner-lane exp (1 MUFU), weight broadcast (8 shfl), f32x2 packed FMAs.
__global__ __launch_bounds__(256, 2)
void k_attn(const float* __restrict__ x,
            const float* __restrict__ Wv, const float* __restrict__ bv,
            const float* __restrict__ spd_w) {
    int d = blockIdx.x;
    int t = threadIdx.x, lane = t & 31, wp = t >> 5;
    __shared__ __align__(16) float us[H][C];
    __shared__ __align__(16) float agg[H][C];
    __shared__ float csw[5 * H];
    __shared__ float lsh[H];
    __shared__ float Linv[H];

    for (int i = t; i < H * C; i += 256) {
        ((float*)us)[i] = g_u[d * H * C + i];
        ((float*)agg)[i] = 0.f;
    }
    if (t < 40) csw[t] = g_c0[d * H + (t & 7)] + spd_w[t];
    if (t < H) lsh[t] = 0.f;
    __syncthreads();

    int start = g_bstart[d], cnt = g_bcount[d];
    if (cnt == 0) {
        for (int i = t; i < C; i += 256) g_outsmall[d * C + i] = 0.f;
        return;
    }
    int end = start + cnt;
    int myh = (lane >> 2) & 7;
    unsigned b4 = (lane >> 4) & 1, b3 = (lane >> 3) & 1, b2 = (lane >> 2) & 1;

    u64 acc2[H][4];
    #pragma unroll
    for (int h = 0; h < H; h++)
        #pragma unroll
        for (int j = 0; j < 4; j++) acc2[h][j] = 0ull;
    float lsum = 0.f;

    int i = start + wp;
    int2 se = (i < end) ? g_sedge[i] : make_int2(0, 0);

    for (; i < end; i += 8) {
        int s = se.x, eid = se.y;
        if (i + 8 < end) se = g_sedge[i + 8];
        int sp = (int)g_spd[eid];

        const float4* xr = (const float4*)(x + s * C) + lane * 2;
        float4 a = xr[0];
        float4 b = xr[1];
        u64 xv2[4];
        xv2[0] = pack2(a.x, a.y); xv2[1] = pack2(a.z, a.w);
        xv2[2] = pack2(b.x, b.y); xv2[3] = pack2(b.z, b.w);

        // per-head partial dot over this lane's 8 channels (packed)
        float p[H];
        #pragma unroll
        for (int h = 0; h < H; h++) {
            const ulonglong2* up = (const ulonglong2*)&us[h][lane * 8];
            ulonglong2 ua = up[0], ub = up[1];
            u64 q2 = 0ull;
            fma2(q2, xv2[0], ua.x);
            fma2(q2, xv2[1], ua.y);
            fma2(q2, xv2[2], ub.x);
            fma2(q2, xv2[3], ub.y);
            float lo, hi; unpack2(q2, lo, hi);
            p[h] = lo + hi;
        }

        // head-folding butterfly: 9 shfls total
        float r4[4];
        #pragma unroll
        for (int j = 0; j < 4; j++) {
            float mine = b4 ? p[j + 4] : p[j];
            float send = b4 ? p[j] : p[j + 4];
            r4[j] = mine + __shfl_xor_sync(0xffffffffu, send, 16);
        }
        float r2[2];
        #pragma unroll
        for (int j = 0; j < 2; j++) {
            float mine = b3 ? r4[j + 2] : r4[j];
            float send = b3 ? r4[j] : r4[j + 2];
            r2[j] = mine + __shfl_xor_sync(0xffffffffu, send, 8);
        }
        {
            float mine = b2 ? r2[1] : r2[0];
            float send = b2 ? r2[0] : r2[1];
            r2[0] = mine + __shfl_xor_sync(0xffffffffu, send, 4);
        }
        r2[0] += __shfl_xor_sync(0xffffffffu, r2[0], 2);
        r2[0] += __shfl_xor_sync(0xffffffffu, r2[0], 1);
        // lane now holds full score for head myh

        float wv = __expf(r2[0] + csw[sp * H + myh]);
        lsum += wv;

        // broadcast weights + packed accumulator update
        #pragma unroll
        for (int h = 0; h < H; h++) {
            float wh = __shfl_sync(0xffffffffu, wv, h * 4);
            u64 w2 = pack2(wh, wh);
            fma2(acc2[h][0], w2, xv2[0]);
            fma2(acc2[h][1], w2, xv2[1]);
            fma2(acc2[h][2], w2, xv2[2]);
            fma2(acc2[h][3], w2, xv2[3]);
        }
    }

    // combine warps
    #pragma unroll
    for (int h = 0; h < H; h++)
        #pragma unroll
        for (int j = 0; j < 4; j++) {
            float lo, hi; unpack2(acc2[h][j], lo, hi);
            atomicAdd(&agg[h][lane * 8 + 2 * j], lo);
            atomicAdd(&agg[h][lane * 8 + 2 * j + 1], hi);
        }
    if ((lane & 3) == 0) atomicAdd(&lsh[myh], lsum);
    __syncthreads();
    if (t < H) Linv[t] = 1.f / lsh[t];
    __syncthreads();
    for (int idx = t; idx < H * C; idx += 256)
        ((float*)agg)[idx] *= Linv[idx >> 8];
    __syncthreads();

    // out[c] = agg[c/32] . Wv[c,:] + bv[c]
    for (int r = 0; r < 32; r++) {
        int c = wp * 32 + r;
        const float4* wr = (const float4*)(Wv + c * C) + lane * 2;
        float4 wa = wr[0], wb = wr[1];
        const float* ar = &agg[wp][lane * 8];
        float pacc = wa.x * ar[0] + wa.y * ar[1] + wa.z * ar[2] + wa.w * ar[3]
                   + wb.x * ar[4] + wb.y * ar[5] + wb.z * ar[6] + wb.w * ar[7];
        #pragma unroll
        for (int o = 16; o; o >>= 1) pacc += __shfl_xor_sync(0xffffffffu, pacc, o);
        if (lane == 0) g_outsmall[d * C + c] = pacc + bv[c];
    }
}

// ---------------------------------------------------------------------------
// K7: residual + degree + LayerNorm, one warp per row
__global__ void k_ln(const float* __restrict__ x,
                     const float* __restrict__ gamma, const float* __restrict__ beta,
                     float* __restrict__ out, int n) {
    int row = blockIdx.x * 8 + (threadIdx.x >> 5);
    int lane = threadIdx.x & 31;
    if (row >= n) return;
    const float* xr = x + (size_t)row * C + lane * 8;
    float4 a = *(const float4*)(xr);
    float4 b = *(const float4*)(xr + 4);
    float v[8] = {a.x, a.y, a.z, a.w, b.x, b.y, b.z, b.w};
    float degf = (float)g_deg[row];
    #pragma unroll
    for (int j = 0; j < 8; j++) v[j] += degf;
    if (row < NUM_DST) {
        const float* orow = g_outsmall + row * C + lane * 8;
        float4 oa = *(const float4*)(orow);
        float4 ob = *(const float4*)(orow + 4);
        v[0] += oa.x; v[1] += oa.y; v[2] += oa.z; v[3] += oa.w;
        v[4] += ob.x; v[5] += ob.y; v[6] += ob.z; v[7] += ob.w;
    }
    float s = 0.f;
    #pragma unroll
    for (int j = 0; j < 8; j++) s += v[j];
    #pragma unroll
    for (int o = 16; o; o >>= 1) s += __shfl_xor_sync(0xffffffffu, s, o);
    float mu = s * (1.f / C);
    float q = 0.f;
    #pragma unroll
    for (int j = 0; j < 8; j++) { float dd = v[j] - mu; q += dd * dd; }
    #pragma unroll
    for (int o = 16; o; o >>= 1) q += __shfl_xor_sync(0xffffffffu, q, o);
    float rstd = rsqrtf(q * (1.f / C) + LN_EPS);
    const float* gr = gamma + lane * 8;
    const float* br = beta + lane * 8;
    float4 g1 = *(const float4*)(gr);
    float4 g2 = *(const float4*)(gr + 4);
    float4 b1 = *(const float4*)(br);
    float4 b2 = *(const float4*)(br + 4);
    float gv[8] = {g1.x, g1.y, g1.z, g1.w, g2.x, g2.y, g2.z, g2.w};
    float bvv[8] = {b1.x, b1.y, b1.z, b1.w, b2.x, b2.y, b2.z, b2.w};
    float o[8];
    #pragma unroll
    for (int j = 0; j < 8; j++) o[j] = (v[j] - mu) * rstd * gv[j] + bvv[j];
    float* orow = out + (size_t)row * C + lane * 8;
    *(float4*)(orow) = make_float4(o[0], o[1], o[2], o[3]);
    *(float4*)(orow + 4) = make_float4(o[4], o[5], o[6], o[7]);
}

// ---------------------------------------------------------------------------
extern "C" void kernel_launch(void* const* d_in, const int* in_sizes, int n_in,
                              void* d_out, int out_size) {
    const float* x     = (const float*)d_in[0];
    const int*   src   = (const int*)d_in[1];
    const int*   dst   = (const int*)d_in[2];
    const float* Wq    = (const float*)d_in[3];
    const float* bq    = (const float*)d_in[4];
    const float* Wk    = (const float*)d_in[5];
    const float* bk    = (const float*)d_in[6];
    const float* Wv    = (const float*)d_in[7];
    const float* bv    = (const float*)d_in[8];
    const float* spd_w = (const float*)d_in[9];
    const float* gamma = (const float*)d_in[10];
    const float* beta  = (const float*)d_in[11];
    float* out = (float*)d_out;

    int n = in_sizes[0] / C;
    int e = in_sizes[1];
    int mx = (n > e) ? n : e;

    k_init<<<(mx + 255) / 256, 256>>>(n, e);
    k_hist<<<HB, 256>>>(src, dst, e);
    k_prefix<<<1, 256>>>();
    k_scatter<<<HB, 256>>>(src, dst, e);
    k_bfs<<<1, 256>>>(src, dst);
    k_qu<<<NUM_DST, 256>>>(x, Wq, bq, Wk, bk);
    k_attn<<<NUM_DST, 256>>>(x, Wv, bv, spd_w);
    k_ln<<<(n + 7) / 8, 256>>>(x, gamma, beta, out, n);
}